// round 14
// baseline (speedup 1.0000x reference)
#include <cuda_runtime.h>

// E3nnSimpleNodeBlock: out = TensorSquare(feats+msgs), N=131072, MUL=16.
// Round 13: f32x2 over COMPONENTS of one node (not two nodes!). FFMA2 rt equals
// FFMA rt, so packing components halves fma-pipe instruction count at scalar-kernel
// register cost. pa[u]=(x1u0,x1u1), pb[u]=(x1u2,x0u), px0=(x0 pairs). Weight slab
// pre-arranged so pairs/splats come straight out of LDS.128/LDS.64. Same folded
// algorithm, sched fences, cp.async slab, staged float4 flush. launch_bounds(128,3).

#define T 128
#define NODES_PER_BLOCK 128   // 1 node per thread
#define NNODES 131072

typedef unsigned long long u64;

// Per-w slab, 1344 floats:
//  [0,1088)    : per-tri 8-float group {q112,q000,q110,q110,q112,q112,0,0}
//  [1088,1344) : A101*W101[u][v] at 1088 + u*16 + v
__device__ __align__(16) float PW[16 * 1344];

// ---------- f32x2 helpers ----------
__device__ __forceinline__ u64 f2fma(u64 a, u64 b, u64 c) {
    u64 d;
    asm("fma.rn.f32x2 %0, %1, %2, %3;" : "=l"(d) : "l"(a), "l"(b), "l"(c));
    return d;
}
__device__ __forceinline__ u64 fpack(float lo, float hi) {
    u64 d;
    asm("mov.b64 %0, {%1, %2};" : "=l"(d) : "f"(lo), "f"(hi));
    return d;
}
__device__ __forceinline__ void funpack(u64 p, float& lo, float& hi) {
    asm("mov.b64 {%0, %1}, %2;" : "=f"(lo), "=f"(hi) : "l"(p));
}
__device__ __forceinline__ void sched_fence() { asm volatile("" ::: "memory"); }

// ---------- weight prep ----------
__global__ void prep_kernel(const float* __restrict__ w000, const float* __restrict__ w101,
                            const float* __restrict__ w110, const float* __restrict__ w112) {
    int idx = blockIdx.x * blockDim.x + threadIdx.x;   // 0 .. 16*1344-1
    if (idx >= 16 * 1344) return;
    int w = idx / 1344;
    int slot = idx - w * 1344;
    const float A000 = 0.04419417382415922f;           // sqrt(1/(2*MUL*MUL))
    const float A110 = 0.02551551815399144f;           // A000/sqrt(3)
    const float A101 = 0.0625f;                        // sqrt(3/MUL^2)/sqrt(3)
    const float A112 = 0.13975424859373686f;           // sqrt(5)/16

    float val = 0.0f;
    if (slot < 1088) {
        int tri = slot >> 3, j = slot & 7;
        int v = 0;
        while ((v + 1) * (v + 2) / 2 <= tri) v++;
        int u = tri - v * (v + 1) / 2;
        int iuv = u * 256 + v * 16 + w;
        int ivu = v * 256 + u * 16 + w;
        // j: 0->q112, 1->q000, 2,3->q110, 4,5->q112, 6,7->0
        const float* src = (j == 1) ? w000 : (j == 2 || j == 3) ? w110
                          : (j == 0 || j == 4 || j == 5) ? w112 : nullptr;
        if (src) {
            float A = (j == 1) ? A000 : (j == 2 || j == 3) ? A110 : A112;
            val = (u == v) ? A * src[iuv] : A * (src[iuv] + src[ivu]);
        }
    } else {
        int s = slot - 1088;
        int u = s >> 4, v = s & 15;
        val = A101 * w101[u * 256 + v * 16 + w];
    }
    PW[idx] = val;
}

// ---------- main kernel ----------
__global__ __launch_bounds__(T, 3) void e3nn_kernel(const float* __restrict__ feats,
                                                    const float* __restrict__ msgs,
                                                    float* __restrict__ out) {
    // SMEM (~28.5 KB/CTA): wbuf double-buffered slab + output staging
    __shared__ __align__(16) float wbuf[2][1344];
    __shared__ __align__(16) float stage[NODES_PER_BLOCK * 36];

    const int t = threadIdx.x;
    const long node = (long)blockIdx.x * NODES_PER_BLOCK + t;

    // ---- load x = feats + msgs; build packed views ----
    u64 pa[16];    // (x1[u][0], x1[u][1])
    u64 pb[16];    // (x1[u][2], x0[u])
    u64 px0[8];    // (x0[2g], x0[2g+1])
    {
        float xA[64];
        const float4* fA = reinterpret_cast<const float4*>(feats) + node * 16;
        const float4* mA = reinterpret_cast<const float4*>(msgs) + node * 16;
#pragma unroll
        for (int q = 0; q < 16; ++q) {
            float4 f = fA[q], m = mA[q];
            xA[4 * q + 0] = f.x + m.x; xA[4 * q + 1] = f.y + m.y;
            xA[4 * q + 2] = f.z + m.z; xA[4 * q + 3] = f.w + m.w;
        }
#pragma unroll
        for (int u = 0; u < 16; ++u) {
            pa[u] = fpack(xA[16 + 3 * u + 0], xA[16 + 3 * u + 1]);
            pb[u] = fpack(xA[16 + 3 * u + 2], xA[u]);
        }
#pragma unroll
        for (int g = 0; g < 8; ++g) px0[g] = fpack(xA[2 * g], xA[2 * g + 1]);
    }

    // ---- cp.async weight staging: 1344 floats = 336 x 16B chunks ----
#define STAGE_SLAB(wi, buf)                                                               \
    do {                                                                                  \
        const float* srcb = PW + (wi) * 1344;                                             \
        float* dstb = wbuf[(buf)];                                                        \
        unsigned s0 = (unsigned)__cvta_generic_to_shared(dstb + 4 * t);                   \
        asm volatile("cp.async.cg.shared.global [%0], [%1], 16;" ::"r"(s0), "l"(srcb + 4 * t)); \
        asm volatile("cp.async.cg.shared.global [%0], [%1], 16;" ::"r"(s0 + 2048), "l"(srcb + 512 + 4 * t)); \
        if (t < 80) {                                                                     \
            asm volatile("cp.async.cg.shared.global [%0], [%1], 16;" ::"r"(s0 + 4096), "l"(srcb + 1024 + 4 * t)); \
        }                                                                                 \
        asm volatile("cp.async.commit_group;");                                           \
    } while (0)

    STAGE_SLAB(0, 0);
    asm volatile("cp.async.wait_group 0;");
    __syncthreads();

    const float CS2 = 0.31622776601683794f;   // 1/sqrt(10)
    const float C62 = 0.18257418583505536f;   // 1/sqrt(30)

#pragma unroll 1
    for (int w = 0; w < 16; ++w) {
        if (w < 15) STAGE_SLAB(w + 1, (w + 1) & 1);

        const float* __restrict__ cw = wbuf[w & 1];
        const ulonglong2* __restrict__ grp = reinterpret_cast<const ulonglong2*>(cw);   // [tri] -> ull2 pair of 8-float group
        const u64* __restrict__ grpTail = reinterpret_cast<const u64*>(cw);             // ull idx 4*tri+2 = (q112,q112)
        const ulonglong2* __restrict__ w101p =
            reinterpret_cast<const ulonglong2*>(cw + 1088);                             // [u*4 + j]

        // packed accumulators
        u64 P01 = 0, QA = 0, QB = 0, ACP = 0, AC01 = 0, A1001 = 0;
        float P2 = 0.f, A12 = 0.f;

        // ---- symmetric paths: triangular u <= v ----
#pragma unroll
        for (int v = 0; v < 16; ++v) {
            sched_fence();
            const int tb = v * (v + 1) / 2;
            u64 sb = 0;        // (s112_2, s000)
            u64 s11001 = 0;    // (s110_0, s110_1)
            u64 s11201 = 0;    // (s112_0, s112_1)
            float s110_2 = 0.f;
#pragma unroll
            for (int u = 0; u <= v; ++u) {
                ulonglong2 g2 = grp[(tb + u) * 2];       // LDS.128: lo=(q112,q000), hi=(q110,q110)
                u64 qs = grpTail[(tb + u) * 4 + 2];      // LDS.64: (q112,q112)
                sb     = f2fma(g2.x, pb[u], sb);
                s11001 = f2fma(g2.y, pa[u], s11001);
                s11201 = f2fma(qs, pa[u], s11201);
                float q110, dummy, x1u2, xu0;
                funpack(g2.y, q110, dummy);
                funpack(pb[u], x1u2, xu0);
                s110_2 = fmaf(q110, x1u2, s110_2);
            }
            // ---- stage-2 (v static, register-direct) ----
            float s112_2, s000; funpack(sb, s112_2, s000);
            float pav0, pav1;   funpack(pa[v], pav0, pav1);
            float x1v2, x0v;    funpack(pb[v], x1v2, x0v);

            P01  = f2fma(s11201, pa[v], P01);                       // (P0,P1)
            QA   = f2fma(s11201, fpack(pav1, pav0), QA);            // swap -> Q01 lanes
            QB   = f2fma(s11201, fpack(x1v2, x1v2), QB);            // (Q02,Q12) part1
            QB   = f2fma(fpack(s112_2, s112_2), pa[v], QB);         // (Q02,Q12) part2
            ACP  = f2fma(fpack(s110_2, s000), pb[v], ACP);          // (acc01_2, acc00)
            AC01 = f2fma(s11001, pa[v], AC01);                      // (acc01_0, acc01_1)
            P2   = fmaf(s112_2, x1v2, P2);
        }

        // ---- 101 path: r[u] = W101[u,:]·x0 ; out1 += r[u]*x1[u] ----
#pragma unroll
        for (int u = 0; u < 16; ++u) {
            sched_fence();
            u64 r2 = 0;
#pragma unroll
            for (int j = 0; j < 4; ++j) {
                ulonglong2 q = w101p[u * 4 + j];       // two weight pairs
                r2 = f2fma(q.x, px0[2 * j + 0], r2);
                r2 = f2fma(q.y, px0[2 * j + 1], r2);
            }
            float rlo, rhi; funpack(r2, rlo, rhi);
            float r = rlo + rhi;
            A1001 = f2fma(fpack(r, r), pa[u], A1001);  // (a10,a11)
            float x1u2, xu0; funpack(pb[u], x1u2, xu0);
            A12 = fmaf(r, x1u2, A12);
        }

        // ---- epilogue for this w -> SMEM staging (group of 4 w's) ----
        {
            const int w2 = w & 3;
            float* sA = stage + t * 36;

            float P0, P1;       funpack(P01, P0, P1);
            float qa0, qa1;     funpack(QA, qa0, qa1);
            float Q02, Q12;     funpack(QB, Q02, Q12);
            float ac12, acc00;  funpack(ACP, ac12, acc00);
            float c0, c1;       funpack(AC01, c0, c1);
            float a10, a11;     funpack(A1001, a10, a11);

            sA[w2] = acc00 + (c0 + c1 + ac12);

            sA[4 + 3 * w2 + 0] = a10;
            sA[4 + 3 * w2 + 1] = a11;
            sA[4 + 3 * w2 + 2] = A12;

            sA[16 + 5 * w2 + 0] = CS2 * (qa0 + qa1);
            sA[16 + 5 * w2 + 1] = CS2 * Q02;
            sA[16 + 5 * w2 + 2] = CS2 * Q12;
            sA[16 + 5 * w2 + 3] = CS2 * (P0 - P1);
            sA[16 + 5 * w2 + 4] = C62 * (2.0f * P2 - P0 - P1);
        }

        // ---- every 4 w's: coalesced float4 flush ----
        if ((w & 3) == 3) {
            __syncthreads();
            const int g = w >> 2;
            const float4* st4 = reinterpret_cast<const float4*>(stage);  // [node][9 f4]
            const long ctaBase = (long)blockIdx.x * NODES_PER_BLOCK;
#pragma unroll
            for (int k = 0; k < 9; ++k) {
                int i = t + k * T;
                int n = i / 9;
                int p = i - n * 9;
                float4 val = st4[i];
                int col = (p == 0) ? (4 * g)
                        : (p < 4)  ? (16 + 12 * g + 4 * (p - 1))
                                   : (64 + 20 * g + 4 * (p - 4));
                *reinterpret_cast<float4*>(out + (ctaBase + n) * 144 + col) = val;
            }
        }

        asm volatile("cp.async.wait_group 0;");
        __syncthreads();
    }
#undef STAGE_SLAB
}

extern "C" void kernel_launch(void* const* d_in, const int* in_sizes, int n_in,
                              void* d_out, int out_size) {
    const float* feats = (const float*)d_in[0];
    const float* msgs  = (const float*)d_in[1];
    const float* w000  = (const float*)d_in[2];
    const float* w101  = (const float*)d_in[3];
    const float* w110  = (const float*)d_in[4];
    const float* w112  = (const float*)d_in[5];
    float* out = (float*)d_out;

    prep_kernel<<<(16 * 1344 + 255) / 256, 256>>>(w000, w101, w110, w112);
    e3nn_kernel<<<NNODES / NODES_PER_BLOCK, T>>>(feats, msgs, out);
}